// round 5
// baseline (speedup 1.0000x reference)
#include <cuda_runtime.h>
#include <cstdint>

#define N_CATS 8
#define NBLOCKS 888            // 6 CTAs/SM * 148 SMs = one persistent wave
#define NTHREADS 256

// Device-global scratch: 8x8 confusion-matrix counts + arrival ticket.
// Zero at load; finalizing block resets them so every graph replay is clean.
__device__ unsigned int g_cm[64];
__device__ unsigned int g_done;

__global__ __launch_bounds__(NTHREADS, 6) void qwk_fused_kernel(
    const float4* __restrict__ logits4,   // 2 float4 per element
    const int* __restrict__ targets,      // int32
    float* __restrict__ out,
    int n_pairs)                          // n_elems / 2
{
    __shared__ unsigned int s_cm[64];
    __shared__ bool s_is_last;
    int tid = threadIdx.x;
    if (tid < 64) s_cm[tid] = 0u;
    __syncthreads();

    const int2* targets2 = (const int2*)targets;
    int stride = gridDim.x * blockDim.x;

    for (int j = blockIdx.x * blockDim.x + tid; j < n_pairs; j += stride) {
        float4 a0 = __ldcs(&logits4[4 * j + 0]);
        float4 b0 = __ldcs(&logits4[4 * j + 1]);
        float4 a1 = __ldcs(&logits4[4 * j + 2]);
        float4 b1 = __ldcs(&logits4[4 * j + 3]);
        int2 tv2 = __ldcs(&targets2[j]);

        // argmax elem 0 (first-max-wins, strict >)
        int best0 = 0; float m0 = a0.x;
        if (a0.y > m0) { m0 = a0.y; best0 = 1; }
        if (a0.z > m0) { m0 = a0.z; best0 = 2; }
        if (a0.w > m0) { m0 = a0.w; best0 = 3; }
        if (b0.x > m0) { m0 = b0.x; best0 = 4; }
        if (b0.y > m0) { m0 = b0.y; best0 = 5; }
        if (b0.z > m0) { m0 = b0.z; best0 = 6; }
        if (b0.w > m0) { m0 = b0.w; best0 = 7; }

        // argmax elem 1
        int best1 = 0; float m1 = a1.x;
        if (a1.y > m1) { m1 = a1.y; best1 = 1; }
        if (a1.z > m1) { m1 = a1.z; best1 = 2; }
        if (a1.w > m1) { m1 = a1.w; best1 = 3; }
        if (b1.x > m1) { m1 = b1.x; best1 = 4; }
        if (b1.y > m1) { m1 = b1.y; best1 = 5; }
        if (b1.z > m1) { m1 = b1.z; best1 = 6; }
        if (b1.w > m1) { m1 = b1.w; best1 = 7; }

        if ((unsigned)(tv2.x - 1) < (unsigned)(N_CATS - 1))
            atomicAdd(&s_cm[tv2.x * N_CATS + best0], 1u);
        if ((unsigned)(tv2.y - 1) < (unsigned)(N_CATS - 1))
            atomicAdd(&s_cm[tv2.y * N_CATS + best1], 1u);
    }
    __syncthreads();

    // Flush block histogram to global.
    if (tid < 64) {
        unsigned int c = s_cm[tid];
        if (c) atomicAdd(&g_cm[tid], c);
    }

    // Ticket: last block to arrive finalizes.
    __threadfence();
    __syncthreads();
    if (tid == 0) {
        unsigned int rank = atomicAdd(&g_done, 1u);
        s_is_last = (rank == gridDim.x - 1);
    }
    __syncthreads();
    if (!s_is_last) return;

    if (tid == 0) {
        __threadfence();  // acquire: see all blocks' g_cm atomics

        float cm[64];
        float n = 0.0f;
        #pragma unroll
        for (int i = 0; i < 64; i++) {
            unsigned int c = atomicAdd(&g_cm[i], 0u);   // coherent read
            cm[i] = (float)c;
            n += cm[i];
        }

        float loss;
        if (n == 0.0f) {
            loss = 0.0f;   // qwk = 1 -> loss 0
        } else {
            float inv_n = 1.0f / n;
            #pragma unroll
            for (int i = 0; i < 64; i++) cm[i] *= inv_n;

            float mt[8], mp[8];
            #pragma unroll
            for (int i = 0; i < 8; i++) { mt[i] = 0.0f; mp[i] = 0.0f; }
            #pragma unroll
            for (int i = 0; i < 8; i++)
                #pragma unroll
                for (int jj = 0; jj < 8; jj++) {
                    mt[i] += cm[i * 8 + jj];
                    mp[jj] += cm[i * 8 + jj];
                }

            const float inv_d2 = 1.0f / 49.0f;
            float num = 0.0f, den = 0.0f;
            #pragma unroll
            for (int i = 0; i < 8; i++)
                #pragma unroll
                for (int jj = 0; jj < 8; jj++) {
                    float d = (float)(i - jj);
                    float w = 1.0f - d * d * inv_d2;
                    num += w * cm[i * 8 + jj];
                    den += w * mt[i] * mp[jj];
                }

            float qwk = (den == 0.0f) ? 0.0f : (num / den);
            loss = 1.0f - qwk;
        }
        out[0] = loss;

        // Reset scratch for the next graph replay.
        #pragma unroll
        for (int i = 0; i < 64; i++) g_cm[i] = 0u;
        g_done = 0u;
        __threadfence();
    }
}

extern "C" void kernel_launch(void* const* d_in, const int* in_sizes, int n_in,
                              void* d_out, int out_size) {
    const float4* logits4 = (const float4*)d_in[0];
    const int* targets = (const int*)d_in[1];
    float* out = (float*)d_out;
    int n_elems = in_sizes[1];       // B*S = 2048*4096 (even)
    int n_pairs = n_elems >> 1;

    qwk_fused_kernel<<<NBLOCKS, NTHREADS>>>(logits4, targets, out, n_pairs);
}

// round 6
// speedup vs baseline: 1.1635x; 1.1635x over previous
#include <cuda_runtime.h>
#include <cstdint>

#define N_CATS 8
#define NBLOCKS 592            // 4 CTAs/SM * 148 SMs (best measured config)
#define NTHREADS 256

// Device-global scratch: 8x8 confusion-matrix counts + arrival ticket.
// Zero at load; finalizing block resets them so every graph replay is clean.
__device__ unsigned int g_cm[64];
__device__ unsigned int g_done;

__device__ __forceinline__ int argmax8(float4 a, float4 b) {
    int best = 0; float m = a.x;
    if (a.y > m) { m = a.y; best = 1; }
    if (a.z > m) { m = a.z; best = 2; }
    if (a.w > m) { m = a.w; best = 3; }
    if (b.x > m) { m = b.x; best = 4; }
    if (b.y > m) { m = b.y; best = 5; }
    if (b.z > m) { m = b.z; best = 6; }
    if (b.w > m) { m = b.w; best = 7; }
    return best;
}

__global__ __launch_bounds__(NTHREADS, 4) void qwk_fused_kernel(
    const float4* __restrict__ logits4,   // 2 float4 per element
    const int* __restrict__ targets,      // int32
    float* __restrict__ out,
    int n_pairs)                          // n_elems / 2
{
    __shared__ unsigned int s_cm[64];
    __shared__ bool s_is_last;
    const int tid = threadIdx.x;
    const int lane = tid & 31;
    if (tid < 64) s_cm[tid] = 0u;
    __syncthreads();

    // Loop-invariant sign masks for this lane's two bins (lane and lane+32).
    // sgn[k] = (bit k of lane) ? 0 : ~0  for k = 0..4 (bit 5 handled via mb5).
    unsigned sgn[5];
    #pragma unroll
    for (int k = 0; k < 5; k++)
        sgn[k] = (((unsigned)lane >> k) & 1u) - 1u;   // 1 -> 0x0, 0 -> 0xFFFFFFFF

    unsigned cL = 0u, cH = 0u;   // register counters: bins [lane], [lane+32]

    const int2* targets2 = (const int2*)targets;
    const int stride = gridDim.x * blockDim.x;
    const int warp_base = blockIdx.x * NTHREADS + (tid & ~31);

    for (int jb = warp_base; jb < n_pairs; jb += stride) {
        int j = jb + lane;
        bool inb = (j < n_pairs);
        int jc = inb ? j : (n_pairs - 1);   // clamp: safe load for tail lanes

        float4 a0 = __ldcs(&logits4[4 * jc + 0]);
        float4 b0 = __ldcs(&logits4[4 * jc + 1]);
        float4 a1 = __ldcs(&logits4[4 * jc + 2]);
        float4 b1 = __ldcs(&logits4[4 * jc + 3]);
        int2 tv2 = __ldcs(&targets2[jc]);

        int best0 = argmax8(a0, b0);
        int best1 = argmax8(a1, b1);

        unsigned bin0 = (unsigned)tv2.x * 8u + (unsigned)best0;
        unsigned bin1 = (unsigned)tv2.y * 8u + (unsigned)best1;
        bool v0 = inb && ((unsigned)(tv2.x - 1) < 7u);
        bool v1 = inb && ((unsigned)(tv2.y - 1) < 7u);

        // ---- round 0: 32 elements, one per lane ----
        {
            unsigned m = __ballot_sync(0xffffffffu, v0);
            unsigned mb5;
            #pragma unroll
            for (int k = 0; k < 5; k++) {
                unsigned mb = __ballot_sync(0xffffffffu, (bin0 >> k) & 1u);
                m &= mb ^ sgn[k];
            }
            mb5 = __ballot_sync(0xffffffffu, (bin0 >> 5) & 1u);
            cL += __popc(m & ~mb5);
            cH += __popc(m & mb5);
        }
        // ---- round 1 ----
        {
            unsigned m = __ballot_sync(0xffffffffu, v1);
            unsigned mb5;
            #pragma unroll
            for (int k = 0; k < 5; k++) {
                unsigned mb = __ballot_sync(0xffffffffu, (bin1 >> k) & 1u);
                m &= mb ^ sgn[k];
            }
            mb5 = __ballot_sync(0xffffffffu, (bin1 >> 5) & 1u);
            cL += __popc(m & ~mb5);
            cH += __popc(m & mb5);
        }
    }

    // Per-warp flush: 2 shared atomics per lane, once per kernel.
    if (cL) atomicAdd(&s_cm[lane], cL);
    if (cH) atomicAdd(&s_cm[lane + 32], cH);
    __syncthreads();

    // Block flush to global.
    if (tid < 64) {
        unsigned int c = s_cm[tid];
        if (c) atomicAdd(&g_cm[tid], c);
    }

    // Ticket: last block to arrive finalizes.
    __threadfence();
    __syncthreads();
    if (tid == 0) {
        unsigned int rank = atomicAdd(&g_done, 1u);
        s_is_last = (rank == gridDim.x - 1);
    }
    __syncthreads();
    if (!s_is_last) return;

    if (tid == 0) {
        __threadfence();  // acquire: see all blocks' g_cm atomics

        float cm[64];
        float n = 0.0f;
        #pragma unroll
        for (int i = 0; i < 64; i++) {
            unsigned int c = atomicAdd(&g_cm[i], 0u);   // coherent read
            cm[i] = (float)c;
            n += cm[i];
        }

        float loss;
        if (n == 0.0f) {
            loss = 0.0f;   // qwk = 1 -> loss 0
        } else {
            float inv_n = 1.0f / n;
            #pragma unroll
            for (int i = 0; i < 64; i++) cm[i] *= inv_n;

            float mt[8], mp[8];
            #pragma unroll
            for (int i = 0; i < 8; i++) { mt[i] = 0.0f; mp[i] = 0.0f; }
            #pragma unroll
            for (int i = 0; i < 8; i++)
                #pragma unroll
                for (int jj = 0; jj < 8; jj++) {
                    mt[i] += cm[i * 8 + jj];
                    mp[jj] += cm[i * 8 + jj];
                }

            const float inv_d2 = 1.0f / 49.0f;
            float num = 0.0f, den = 0.0f;
            #pragma unroll
            for (int i = 0; i < 8; i++)
                #pragma unroll
                for (int jj = 0; jj < 8; jj++) {
                    float d = (float)(i - jj);
                    float w = 1.0f - d * d * inv_d2;
                    num += w * cm[i * 8 + jj];
                    den += w * mt[i] * mp[jj];
                }

            float qwk = (den == 0.0f) ? 0.0f : (num / den);
            loss = 1.0f - qwk;
        }
        out[0] = loss;

        // Reset scratch for the next graph replay.
        #pragma unroll
        for (int i = 0; i < 64; i++) g_cm[i] = 0u;
        g_done = 0u;
        __threadfence();
    }
}

extern "C" void kernel_launch(void* const* d_in, const int* in_sizes, int n_in,
                              void* d_out, int out_size) {
    const float4* logits4 = (const float4*)d_in[0];
    const int* targets = (const int*)d_in[1];
    float* out = (float*)d_out;
    int n_elems = in_sizes[1];       // B*S = 2048*4096 (even)
    int n_pairs = n_elems >> 1;

    qwk_fused_kernel<<<NBLOCKS, NTHREADS>>>(logits4, targets, out, n_pairs);
}